// round 2
// baseline (speedup 1.0000x reference)
#include <cuda_runtime.h>

#define DD 128
#define NMAX 50000
#define EMAX 640000

__device__ __align__(16) float g_Hq[NMAX * DD];
__device__ __align__(16) float g_Hr[NMAX * DD];
__device__ __align__(16) float g_Vh[NMAX * DD];
__device__ __align__(16) float g_Hu[NMAX * DD];
__device__ __align__(16) float g_agg[NMAX * DD];
__device__ __align__(16) float g_ehat[(size_t)EMAX * DD];
__device__ __align__(16) float g_stats[4 * DD];  // sum_e, ssq_e, sum_n, ssq_n
__device__ __align__(16) float g_bnp[4 * DD];    // scale_e, shift_e, scale_n, shift_n

typedef unsigned long long u64;

__device__ __forceinline__ u64 pk2(float x, float y) {
    u64 r; asm("mov.b64 %0, {%1,%2};" : "=l"(r) : "f"(x), "f"(y)); return r;
}
__device__ __forceinline__ void fma2(u64& d, u64 a, u64 b) {
    asm("fma.rn.f32x2 %0, %1, %2, %0;" : "+l"(d) : "l"(a), "l"(b));
}
__device__ __forceinline__ float2 up2(u64 v) {
    float2 f; asm("mov.b64 {%0,%1}, %2;" : "=f"(f.x), "=f"(f.y) : "l"(v)); return f;
}
__device__ __forceinline__ void red4(float* p, float a, float b, float c, float d) {
    asm volatile("red.global.add.v4.f32 [%0], {%1,%2,%3,%4};"
                 :: "l"(p), "f"(a), "f"(b), "f"(c), "f"(d) : "memory");
}
__device__ __forceinline__ float sigm(float x) { return 1.0f / (1.0f + __expf(-x)); }

// 128x128x128 tile GEMM. AsT: k-major A (AsT[k*128+r]), Ws: row-major weight.
// Thread (tx,ty): cols tx*8..+7, rows ty*8..+7.
template <bool SWZ>
__device__ __forceinline__ void gemm128(const float* __restrict__ AsT,
                                        const float* __restrict__ Ws,
                                        int tx, int ty, u64 acc[8][4]) {
#pragma unroll 8
    for (int k = 0; k < DD; ++k) {
        float4 b0 = *(const float4*)(Ws + k * DD + tx * 8);
        float4 b1 = *(const float4*)(Ws + k * DD + tx * 8 + 4);
        u64 bb0 = pk2(b0.x, b0.y), bb1 = pk2(b0.z, b0.w);
        u64 bb2 = pk2(b1.x, b1.y), bb3 = pk2(b1.z, b1.w);
        float4 a0, a1;
        if (SWZ) {
            int key = (k >> 3) & 7;
            a0 = *(const float4*)(AsT + k * DD + (((ty * 2) ^ key) << 2));
            a1 = *(const float4*)(AsT + k * DD + (((ty * 2 + 1) ^ key) << 2));
        } else {
            a0 = *(const float4*)(AsT + k * DD + ty * 8);
            a1 = *(const float4*)(AsT + k * DD + ty * 8 + 4);
        }
        float av[8] = {a0.x, a0.y, a0.z, a0.w, a1.x, a1.y, a1.z, a1.w};
#pragma unroll
        for (int i = 0; i < 8; ++i) {
            u64 aa = pk2(av[i], av[i]);
            fma2(acc[i][0], aa, bb0);
            fma2(acc[i][1], aa, bb1);
            fma2(acc[i][2], aa, bb2);
            fma2(acc[i][3], aa, bb3);
        }
    }
}

__device__ __forceinline__ void zero_acc(u64 acc[8][4]) {
#pragma unroll
    for (int i = 0; i < 8; ++i)
#pragma unroll
        for (int j = 0; j < 4; ++j) acc[i][j] = 0ull;
}

// transpose-load a 128-row tile of src (row-major [*,128]) into AsT, 0-pad past nrows
__device__ __forceinline__ void load_T(const float* __restrict__ src, long long r0,
                                       long long nrows, float* __restrict__ AsT, int tid) {
    int r = tid & 127, kh = tid >> 7;
    long long row = r0 + r;
    if (row < nrows) {
        const float4* p = (const float4*)(src + row * DD) + kh * 16;
#pragma unroll
        for (int m = 0; m < 16; ++m) {
            float4 v = p[m];
            int k = kh * 64 + m * 4;
            AsT[(k) * DD + r] = v.x; AsT[(k + 1) * DD + r] = v.y;
            AsT[(k + 2) * DD + r] = v.z; AsT[(k + 3) * DD + r] = v.w;
        }
    } else {
#pragma unroll
        for (int m = 0; m < 16; ++m) {
            int k = kh * 64 + m * 4;
            AsT[(k) * DD + r] = 0.f; AsT[(k + 1) * DD + r] = 0.f;
            AsT[(k + 2) * DD + r] = 0.f; AsT[(k + 3) * DD + r] = 0.f;
        }
    }
}

// ---------------- node GEMMs: Hq/Hr/Vh/Hu = h @ {Q,R,V,U} -------------------
__global__ void __launch_bounds__(256, 1)
k_node_gemm(const float* __restrict__ h, const float* __restrict__ Qw,
            const float* __restrict__ Rw, const float* __restrict__ Vw,
            const float* __restrict__ Uw, int N) {
    extern __shared__ float sm[];
    float* AsT = sm;
    float* Ws  = sm + 16384;
    const int tid = threadIdx.x;
    const int wsel = blockIdx.y;
    const float* W = (wsel == 0) ? Qw : (wsel == 1) ? Rw : (wsel == 2) ? Vw : Uw;
    float* Out     = (wsel == 0) ? g_Hq : (wsel == 1) ? g_Hr : (wsel == 2) ? g_Vh : g_Hu;
    const long long n0 = (long long)blockIdx.x * DD;

    for (int t = tid; t < DD * DD / 4; t += 256)
        ((float4*)Ws)[t] = ((const float4*)W)[t];
    load_T(h, n0, N, AsT, tid);
    __syncthreads();

    const int tx = tid & 15, ty = tid >> 4;
    u64 acc[8][4];
    zero_acc(acc);
    gemm128<false>(AsT, Ws, tx, ty, acc);

    const int cb = tx * 8;
#pragma unroll
    for (int i = 0; i < 8; ++i) {
        long long row = n0 + ty * 8 + i;
        if (row < N) {
            float2 p0 = up2(acc[i][0]), p1 = up2(acc[i][1]);
            float2 p2 = up2(acc[i][2]), p3 = up2(acc[i][3]);
            float* op = Out + (size_t)row * DD + cb;
            *(float4*)op       = make_float4(p0.x, p0.y, p1.x, p1.y);
            *(float4*)(op + 4) = make_float4(p2.x, p2.y, p3.x, p3.y);
        }
    }
}

// ---- edge: ehat = e@P + Hq[src] + Hr[dst]; sigmoid gate scatter; BN-e stats
__global__ void __launch_bounds__(256, 1)
k_edge_ehat(const float* __restrict__ e, const int* __restrict__ src,
            const int* __restrict__ dst, const float* __restrict__ Pw, int E) {
    extern __shared__ float sm[];
    float* AsT = sm;
    float* Ws  = sm + 16384;
    __shared__ int   s_src[DD], s_dst[DD];
    __shared__ float s_sum[DD], s_ssq[DD];

    const int tid = threadIdx.x;
    const long long e0 = (long long)blockIdx.x * DD;

    for (int t = tid; t < DD * DD / 4; t += 256)
        ((float4*)Ws)[t] = ((const float4*)Pw)[t];
    load_T(e, e0, E, AsT, tid);
    if (tid < DD) {
        long long row = e0 + tid;
        s_src[tid] = (row < E) ? src[row] : 0;
        s_dst[tid] = (row < E) ? dst[row] : 0;
        s_sum[tid] = 0.f;
        s_ssq[tid] = 0.f;
    }
    __syncthreads();

    const int tx = tid & 15, ty = tid >> 4;
    u64 acc[8][4];
    zero_acc(acc);
    gemm128<false>(AsT, Ws, tx, ty, acc);

    const int cb = tx * 8;
    float lsum[8], lssq[8];
#pragma unroll
    for (int j = 0; j < 8; ++j) { lsum[j] = 0.f; lssq[j] = 0.f; }

#pragma unroll
    for (int i = 0; i < 8; ++i) {
        int rr = ty * 8 + i;
        long long row = e0 + rr;
        if (row < E) {
            const int s = s_src[rr], d2 = s_dst[rr];
            const float* hq  = g_Hq + (size_t)s * DD + cb;
            const float* hr  = g_Hr + (size_t)d2 * DD + cb;
            const float* vhp = g_Vh + (size_t)d2 * DD + cb;
            float4 q0 = *(const float4*)hq, q1 = *(const float4*)(hq + 4);
            float4 r0 = *(const float4*)hr, r1 = *(const float4*)(hr + 4);
            float2 p0 = up2(acc[i][0]), p1 = up2(acc[i][1]);
            float2 p2 = up2(acc[i][2]), p3 = up2(acc[i][3]);
            float v0 = p0.x + q0.x + r0.x, v1 = p0.y + q0.y + r0.y;
            float v2 = p1.x + q0.z + r0.z, v3 = p1.y + q0.w + r0.w;
            float v4 = p2.x + q1.x + r1.x, v5 = p2.y + q1.y + r1.y;
            float v6 = p3.x + q1.z + r1.z, v7 = p3.y + q1.w + r1.w;
            float* eh = g_ehat + (size_t)row * DD + cb;
            *(float4*)eh       = make_float4(v0, v1, v2, v3);
            *(float4*)(eh + 4) = make_float4(v4, v5, v6, v7);
            float4 w0 = *(const float4*)vhp, w1 = *(const float4*)(vhp + 4);
            float* ap = g_agg + (size_t)s * DD + cb;
            red4(ap,     sigm(v0) * w0.x, sigm(v1) * w0.y, sigm(v2) * w0.z, sigm(v3) * w0.w);
            red4(ap + 4, sigm(v4) * w1.x, sigm(v5) * w1.y, sigm(v6) * w1.z, sigm(v7) * w1.w);
            lsum[0] += v0; lssq[0] += v0 * v0;  lsum[1] += v1; lssq[1] += v1 * v1;
            lsum[2] += v2; lssq[2] += v2 * v2;  lsum[3] += v3; lssq[3] += v3 * v3;
            lsum[4] += v4; lssq[4] += v4 * v4;  lsum[5] += v5; lssq[5] += v5 * v5;
            lsum[6] += v6; lssq[6] += v6 * v6;  lsum[7] += v7; lssq[7] += v7 * v7;
        }
    }
#pragma unroll
    for (int j = 0; j < 8; ++j) {
        atomicAdd(&s_sum[cb + j], lsum[j]);
        atomicAdd(&s_ssq[cb + j], lssq[j]);
    }
    __syncthreads();
    if (tid < DD) {
        atomicAdd(&g_stats[tid], s_sum[tid]);
        atomicAdd(&g_stats[DD + tid], s_ssq[tid]);
    }
}

// ---------------- node BN stats over x = Hu + agg ----------------------------
__global__ void k_node_stats(int N) {
    const int tid = threadIdx.x;
    const int c = tid & 127, half = tid >> 7;
    const int rbase = blockIdx.x * DD + half * 64;
    float s = 0.f, q = 0.f;
    for (int i = 0; i < 64; ++i) {
        int r = rbase + i;
        if (r < N) {
            float x = g_Hu[(size_t)r * DD + c] + g_agg[(size_t)r * DD + c];
            s += x;
            q += x * x;
        }
    }
    atomicAdd(&g_stats[2 * DD + c], s);
    atomicAdd(&g_stats[3 * DD + c], q);
}

__global__ void k_bn_final(const float* __restrict__ ge, const float* __restrict__ be,
                           const float* __restrict__ gn, const float* __restrict__ bnb,
                           int E, int N) {
    const int tid = threadIdx.x;
    if (tid < DD) {
        float inv = 1.0f / (float)E;
        float mean = g_stats[tid] * inv;
        float var  = g_stats[DD + tid] * inv - mean * mean;
        float sc   = ge[tid] * rsqrtf(var + 1e-5f);
        g_bnp[tid]      = sc;
        g_bnp[DD + tid] = be[tid] - mean * sc;
    } else if (tid < 2 * DD) {
        int c = tid - DD;
        float inv = 1.0f / (float)N;
        float mean = g_stats[2 * DD + c] * inv;
        float var  = g_stats[3 * DD + c] * inv - mean * mean;
        float sc   = gn[c] * rsqrtf(var + 1e-5f);
        g_bnp[2 * DD + c] = sc;
        g_bnp[3 * DD + c] = bnb[c] - mean * sc;
    }
}

// ---- fused edge MLP: e_new = e + relu(BN(ehat)@W1+b1)@W2 + b2 ---------------
__global__ void __launch_bounds__(256, 1)
k_edge_mlp(const float* __restrict__ e, const float* __restrict__ W1,
           const float* __restrict__ b1, const float* __restrict__ W2,
           const float* __restrict__ b2, float* __restrict__ out_e, int E) {
    extern __shared__ float sm[];
    float* Zs = sm;           // BN(ehat) tile, k-major
    float* Ts = sm + 16384;   // relu hidden tile, k-major, XOR-swizzled chunks
    float* Ws = sm + 32768;   // W1 then W2
    const int tid = threadIdx.x;
    const long long e0 = (long long)blockIdx.x * DD;

    for (int t = tid; t < DD * DD / 4; t += 256)
        ((float4*)Ws)[t] = ((const float4*)W1)[t];

    {   // transpose-load ehat tile with BN applied on the fly
        int r = tid & 127, kh = tid >> 7;
        long long row = e0 + r;
        const float4* ep  = (const float4*)(g_ehat + row * DD) + kh * 16;
        const float4* sc4 = ((const float4*)(g_bnp)) + kh * 16;
        const float4* sh4 = ((const float4*)(g_bnp + DD)) + kh * 16;
        if (row < E) {
#pragma unroll
            for (int m = 0; m < 16; ++m) {
                float4 v = ep[m];
                float4 s = sc4[m];
                float4 t = sh4[m];
                int k = kh * 64 + m * 4;
                Zs[(k) * DD + r]     = fmaf(v.x, s.x, t.x);
                Zs[(k + 1) * DD + r] = fmaf(v.y, s.y, t.y);
                Zs[(k + 2) * DD + r] = fmaf(v.z, s.z, t.z);
                Zs[(k + 3) * DD + r] = fmaf(v.w, s.w, t.w);
            }
        } else {
#pragma unroll
            for (int m = 0; m < 16; ++m) {
                int k = kh * 64 + m * 4;
                Zs[(k) * DD + r] = 0.f; Zs[(k + 1) * DD + r] = 0.f;
                Zs[(k + 2) * DD + r] = 0.f; Zs[(k + 3) * DD + r] = 0.f;
            }
        }
    }
    __syncthreads();

    const int tx = tid & 15, ty = tid >> 4;
    const int cb = tx * 8;
    u64 acc[8][4];
    zero_acc(acc);
    gemm128<false>(Zs, Ws, tx, ty, acc);

    {   // bias + relu, store hidden transposed with XOR chunk swizzle
        float4 b1a = *(const float4*)(b1 + cb);
        float4 b1b = *(const float4*)(b1 + cb + 4);
        float tb[8] = {b1a.x, b1a.y, b1a.z, b1a.w, b1b.x, b1b.y, b1b.z, b1b.w};
        float f[8][8];
#pragma unroll
        for (int i = 0; i < 8; ++i) {
            float2 p0 = up2(acc[i][0]), p1 = up2(acc[i][1]);
            float2 p2 = up2(acc[i][2]), p3 = up2(acc[i][3]);
            f[i][0] = p0.x; f[i][1] = p0.y; f[i][2] = p1.x; f[i][3] = p1.y;
            f[i][4] = p2.x; f[i][5] = p2.y; f[i][6] = p3.x; f[i][7] = p3.y;
        }
        int key = tx & 7;
#pragma unroll
        for (int j = 0; j < 8; ++j) {
            int c = cb + j;
            float4 t0 = make_float4(fmaxf(f[0][j] + tb[j], 0.f), fmaxf(f[1][j] + tb[j], 0.f),
                                    fmaxf(f[2][j] + tb[j], 0.f), fmaxf(f[3][j] + tb[j], 0.f));
            float4 t1 = make_float4(fmaxf(f[4][j] + tb[j], 0.f), fmaxf(f[5][j] + tb[j], 0.f),
                                    fmaxf(f[6][j] + tb[j], 0.f), fmaxf(f[7][j] + tb[j], 0.f));
            *(float4*)(Ts + c * DD + (((ty * 2) ^ key) << 2))     = t0;
            *(float4*)(Ts + c * DD + (((ty * 2 + 1) ^ key) << 2)) = t1;
        }
    }
    __syncthreads();
    for (int t = tid; t < DD * DD / 4; t += 256)
        ((float4*)Ws)[t] = ((const float4*)W2)[t];
    __syncthreads();

    zero_acc(acc);
    gemm128<true>(Ts, Ws, tx, ty, acc);

    float4 b2a = *(const float4*)(b2 + cb);
    float4 b2b = *(const float4*)(b2 + cb + 4);
#pragma unroll
    for (int i = 0; i < 8; ++i) {
        long long row = e0 + ty * 8 + i;
        if (row < E) {
            float2 p0 = up2(acc[i][0]), p1 = up2(acc[i][1]);
            float2 p2 = up2(acc[i][2]), p3 = up2(acc[i][3]);
            const float* ein = e + (size_t)row * DD + cb;
            float4 e0v = *(const float4*)ein, e1v = *(const float4*)(ein + 4);
            float* op = out_e + (size_t)row * DD + cb;
            *(float4*)op = make_float4(p0.x + b2a.x + e0v.x, p0.y + b2a.y + e0v.y,
                                       p1.x + b2a.z + e0v.z, p1.y + b2a.w + e0v.w);
            *(float4*)(op + 4) = make_float4(p2.x + b2b.x + e1v.x, p2.y + b2b.y + e1v.y,
                                             p3.x + b2b.z + e1v.z, p3.y + b2b.w + e1v.w);
        }
    }
}

// ---- node finalize: h_new = h + alpha * (scale_n*(Hu+agg) + shift_n) --------
__global__ void k_node_final(const float* __restrict__ h, const float* __restrict__ alpha,
                             float* __restrict__ out, int N) {
    size_t i = (size_t)blockIdx.x * blockDim.x + threadIdx.x;  // float4 index
    size_t total = (size_t)N * (DD / 4);
    if (i >= total) return;
    int c4 = (int)(i & 31);
    float4 xu = ((const float4*)g_Hu)[i];
    float4 ag = ((const float4*)g_agg)[i];
    float4 sc = ((const float4*)(g_bnp + 2 * DD))[c4];
    float4 sh = ((const float4*)(g_bnp + 3 * DD))[c4];
    float4 hv = ((const float4*)h)[i];
    float a = *alpha;
    float4 o;
    o.x = hv.x + a * fmaf(xu.x + ag.x, sc.x, sh.x);
    o.y = hv.y + a * fmaf(xu.y + ag.y, sc.y, sh.y);
    o.z = hv.z + a * fmaf(xu.z + ag.z, sc.z, sh.z);
    o.w = hv.w + a * fmaf(xu.w + ag.w, sc.w, sh.w);
    ((float4*)out)[i] = o;
}

extern "C" void kernel_launch(void* const* d_in, const int* in_sizes, int n_in,
                              void* d_out, int out_size) {
    const float* h   = (const float*)d_in[0];
    const float* e   = (const float*)d_in[1];
    const int*   ei  = (const int*)d_in[2];
    const float* Pw  = (const float*)d_in[3];
    const float* Qw  = (const float*)d_in[4];
    const float* Rw  = (const float*)d_in[5];
    const float* Uw  = (const float*)d_in[6];
    const float* Vw  = (const float*)d_in[7];
    const float* W1  = (const float*)d_in[8];
    const float* b1  = (const float*)d_in[9];
    const float* W2  = (const float*)d_in[10];
    const float* b2  = (const float*)d_in[11];
    const float* ge  = (const float*)d_in[12];
    const float* be  = (const float*)d_in[13];
    const float* gn  = (const float*)d_in[14];
    const float* bnb = (const float*)d_in[15];
    const float* alpha = (const float*)d_in[16];

    const int N = in_sizes[0] / DD;
    const int E = in_sizes[1] / DD;
    const int* src = ei;
    const int* dst = ei + E;

    float* out_h = (float*)d_out;
    float* out_e = out_h + (size_t)N * DD;

    cudaFuncSetAttribute(k_node_gemm, cudaFuncAttributeMaxDynamicSharedMemorySize, 131072);
    cudaFuncSetAttribute(k_edge_ehat, cudaFuncAttributeMaxDynamicSharedMemorySize, 131072);
    cudaFuncSetAttribute(k_edge_mlp,  cudaFuncAttributeMaxDynamicSharedMemorySize, 196608);

    void *agg_ptr, *stats_ptr;
    cudaGetSymbolAddress(&agg_ptr, g_agg);
    cudaGetSymbolAddress(&stats_ptr, g_stats);
    cudaMemsetAsync(agg_ptr, 0, (size_t)N * DD * sizeof(float), 0);
    cudaMemsetAsync(stats_ptr, 0, 4 * DD * sizeof(float), 0);

    const int nb = (N + DD - 1) / DD;
    const int ebt = (E + DD - 1) / DD;

    k_node_gemm<<<dim3(nb, 4), 256, 131072>>>(h, Qw, Rw, Vw, Uw, N);
    k_edge_ehat<<<ebt, 256, 131072>>>(e, src, dst, Pw, E);
    k_node_stats<<<nb, 256>>>(N);
    k_bn_final<<<1, 256>>>(ge, be, gn, bnb, E, N);
    k_edge_mlp<<<ebt, 256, 196608>>>(e, W1, b1, W2, b2, out_e, E);

    const size_t tot4 = (size_t)N * (DD / 4);
    k_node_final<<<(int)((tot4 + 255) / 256), 256>>>(h, alpha, out_h, N);
}

// round 3
// speedup vs baseline: 1.1728x; 1.1728x over previous
#include <cuda_runtime.h>

#define DD 128
#define RT 256           // rows per tile
#define NMAX 50000
#define EMAX 640000

__device__ __align__(16) float g_Hq[NMAX * DD];
__device__ __align__(16) float g_Hr[NMAX * DD];
__device__ __align__(16) float g_Vh[NMAX * DD];
__device__ __align__(16) float g_Hu[NMAX * DD];
__device__ __align__(16) float g_agg[NMAX * DD];
__device__ __align__(16) float g_ehat[(size_t)EMAX * DD];
__device__ __align__(16) float g_stats[4 * DD];  // sum_e, ssq_e, sum_n, ssq_n
__device__ __align__(16) float g_bnp[4 * DD];    // scale_e, shift_e, scale_n, shift_n

typedef unsigned long long u64;

__device__ __forceinline__ u64 pk2(float x, float y) {
    u64 r; asm("mov.b64 %0, {%1,%2};" : "=l"(r) : "f"(x), "f"(y)); return r;
}
__device__ __forceinline__ void fma2(u64& d, u64 a, u64 b) {
    asm("fma.rn.f32x2 %0, %1, %2, %0;" : "+l"(d) : "l"(a), "l"(b));
}
__device__ __forceinline__ float2 up2(u64 v) {
    float2 f; asm("mov.b64 {%0,%1}, %2;" : "=f"(f.x), "=f"(f.y) : "l"(v)); return f;
}
__device__ __forceinline__ void red4(float* p, float a, float b, float c, float d) {
    asm volatile("red.global.add.v4.f32 [%0], {%1,%2,%3,%4};"
                 :: "l"(p), "f"(a), "f"(b), "f"(c), "f"(d) : "memory");
}
__device__ __forceinline__ float sigm(float x) { return 1.0f / (1.0f + __expf(-x)); }

// 256x128x128 tile GEMM. AsT: k-major A in smem (AsT[k*RT + r]), W: row-major
// weight read straight from global (L1-resident). Thread (tx,ty):
// cols tx*8..+7, rows ty*8..+7. acc[i][jj] = cols (2jj, 2jj+1).
template <bool SWZ>
__device__ __forceinline__ void gemm_g(const float* __restrict__ AsT,
                                       const float* __restrict__ Wg,
                                       int tx, int ty, u64 acc[8][4]) {
    const float4* bp = (const float4*)Wg + tx * 2;  // + k*32 per row
#pragma unroll 4
    for (int k = 0; k < DD; ++k) {
        float4 b0 = __ldg(bp + k * 32);
        float4 b1 = __ldg(bp + k * 32 + 1);
        u64 bb0 = pk2(b0.x, b0.y), bb1 = pk2(b0.z, b0.w);
        u64 bb2 = pk2(b1.x, b1.y), bb3 = pk2(b1.z, b1.w);
        float4 a0, a1;
        if (SWZ) {
            int key = (k >> 3) & 7;
            a0 = *(const float4*)(AsT + k * RT + (((ty * 2) ^ key) << 2));
            a1 = *(const float4*)(AsT + k * RT + (((ty * 2 + 1) ^ key) << 2));
        } else {
            a0 = *(const float4*)(AsT + k * RT + ty * 8);
            a1 = *(const float4*)(AsT + k * RT + ty * 8 + 4);
        }
        float av[8] = {a0.x, a0.y, a0.z, a0.w, a1.x, a1.y, a1.z, a1.w};
#pragma unroll
        for (int i = 0; i < 8; ++i) {
            u64 aa = pk2(av[i], av[i]);
            fma2(acc[i][0], aa, bb0);
            fma2(acc[i][1], aa, bb1);
            fma2(acc[i][2], aa, bb2);
            fma2(acc[i][3], aa, bb3);
        }
    }
}

__device__ __forceinline__ void zero_acc(u64 acc[8][4]) {
#pragma unroll
    for (int i = 0; i < 8; ++i)
#pragma unroll
        for (int j = 0; j < 4; ++j) acc[i][j] = 0ull;
}

// transpose-load a 256-row tile of src (row-major [*,128]) into AsT (k-major)
__device__ __forceinline__ void load_T(const float* __restrict__ src, long long r0,
                                       long long nrows, float* __restrict__ AsT, int tid) {
    int r = tid & 255, kh = tid >> 8;  // kh in {0,1}, 64 k's each
    long long row = r0 + r;
    if (row < nrows) {
        const float4* p = (const float4*)(src + row * DD) + kh * 16;
#pragma unroll
        for (int m = 0; m < 16; ++m) {
            float4 v = p[m];
            int k = kh * 64 + m * 4;
            AsT[(k) * RT + r] = v.x; AsT[(k + 1) * RT + r] = v.y;
            AsT[(k + 2) * RT + r] = v.z; AsT[(k + 3) * RT + r] = v.w;
        }
    } else {
#pragma unroll
        for (int m = 0; m < 16; ++m) {
            int k = kh * 64 + m * 4;
            AsT[(k) * RT + r] = 0.f; AsT[(k + 1) * RT + r] = 0.f;
            AsT[(k + 2) * RT + r] = 0.f; AsT[(k + 3) * RT + r] = 0.f;
        }
    }
}

// ---- node GEMMs: Hq/Hr/Vh/Hu = h @ {Q,R,V,U}; one A-tile load, 4 GEMMs -----
__global__ void __launch_bounds__(512, 1)
k_node_gemm(const float* __restrict__ h, const float* __restrict__ Qw,
            const float* __restrict__ Rw, const float* __restrict__ Vw,
            const float* __restrict__ Uw, int N) {
    extern __shared__ float sm[];
    float* AsT = sm;
    const int tid = threadIdx.x;
    const long long n0 = (long long)blockIdx.x * RT;

    if (blockIdx.x == 0) g_stats[tid] = 0.f;  // fold stats-memset in (512 = 4*DD)

    load_T(h, n0, N, AsT, tid);
    __syncthreads();

    const int tx = tid & 15, ty = tid >> 4;
    const int cb = tx * 8;
    const float* Ws[4] = {Qw, Rw, Vw, Uw};
    float* Outs[4] = {g_Hq, g_Hr, g_Vh, g_Hu};

#pragma unroll 1
    for (int w = 0; w < 4; ++w) {
        u64 acc[8][4];
        zero_acc(acc);
        gemm_g<false>(AsT, Ws[w], tx, ty, acc);
        float* Out = Outs[w];
#pragma unroll
        for (int i = 0; i < 8; ++i) {
            long long row = n0 + ty * 8 + i;
            if (row < N) {
                float2 p0 = up2(acc[i][0]), p1 = up2(acc[i][1]);
                float2 p2 = up2(acc[i][2]), p3 = up2(acc[i][3]);
                float* op = Out + (size_t)row * DD + cb;
                *(float4*)op       = make_float4(p0.x, p0.y, p1.x, p1.y);
                *(float4*)(op + 4) = make_float4(p2.x, p2.y, p3.x, p3.y);
            }
        }
    }
}

// ---- edge: ehat = e@P + Hq[src] + Hr[dst]; sigmoid gate scatter; BN-e stats
__global__ void __launch_bounds__(512, 1)
k_edge_ehat(const float* __restrict__ e, const int* __restrict__ src,
            const int* __restrict__ dst, const float* __restrict__ Pw, int E) {
    extern __shared__ float sm[];
    float* AsT = sm;
    __shared__ int   s_src[RT], s_dst[RT];
    __shared__ float s_sum[DD], s_ssq[DD];

    const int tid = threadIdx.x;
    const long long e0 = (long long)blockIdx.x * RT;

    load_T(e, e0, E, AsT, tid);
    if (tid < RT) {
        long long row = e0 + tid;
        s_src[tid] = (row < E) ? src[row] : 0;
        s_dst[tid] = (row < E) ? dst[row] : 0;
    }
    if (tid < DD) { s_sum[tid] = 0.f; s_ssq[tid] = 0.f; }
    __syncthreads();

    const int tx = tid & 15, ty = tid >> 4;
    u64 acc[8][4];
    zero_acc(acc);
    gemm_g<false>(AsT, Pw, tx, ty, acc);

    const int cb = tx * 8;
    float lsum[8], lssq[8];
#pragma unroll
    for (int j = 0; j < 8; ++j) { lsum[j] = 0.f; lssq[j] = 0.f; }

#pragma unroll
    for (int i = 0; i < 8; ++i) {
        int rr = ty * 8 + i;
        long long row = e0 + rr;
        if (row < E) {
            const int s = s_src[rr], d2 = s_dst[rr];
            const float* hq  = g_Hq + (size_t)s * DD + cb;
            const float* hr  = g_Hr + (size_t)d2 * DD + cb;
            const float* vhp = g_Vh + (size_t)d2 * DD + cb;
            float4 q0 = *(const float4*)hq, q1 = *(const float4*)(hq + 4);
            float4 r0 = *(const float4*)hr, r1 = *(const float4*)(hr + 4);
            float2 p0 = up2(acc[i][0]), p1 = up2(acc[i][1]);
            float2 p2 = up2(acc[i][2]), p3 = up2(acc[i][3]);
            float v0 = p0.x + q0.x + r0.x, v1 = p0.y + q0.y + r0.y;
            float v2 = p1.x + q0.z + r0.z, v3 = p1.y + q0.w + r0.w;
            float v4 = p2.x + q1.x + r1.x, v5 = p2.y + q1.y + r1.y;
            float v6 = p3.x + q1.z + r1.z, v7 = p3.y + q1.w + r1.w;
            float* eh = g_ehat + (size_t)row * DD + cb;
            *(float4*)eh       = make_float4(v0, v1, v2, v3);
            *(float4*)(eh + 4) = make_float4(v4, v5, v6, v7);
            float4 w0 = *(const float4*)vhp, w1 = *(const float4*)(vhp + 4);
            float* ap = g_agg + (size_t)s * DD + cb;
            red4(ap,     sigm(v0) * w0.x, sigm(v1) * w0.y, sigm(v2) * w0.z, sigm(v3) * w0.w);
            red4(ap + 4, sigm(v4) * w1.x, sigm(v5) * w1.y, sigm(v6) * w1.z, sigm(v7) * w1.w);
            lsum[0] += v0; lssq[0] += v0 * v0;  lsum[1] += v1; lssq[1] += v1 * v1;
            lsum[2] += v2; lssq[2] += v2 * v2;  lsum[3] += v3; lssq[3] += v3 * v3;
            lsum[4] += v4; lssq[4] += v4 * v4;  lsum[5] += v5; lssq[5] += v5 * v5;
            lsum[6] += v6; lssq[6] += v6 * v6;  lsum[7] += v7; lssq[7] += v7 * v7;
        }
    }
#pragma unroll
    for (int j = 0; j < 8; ++j) {
        atomicAdd(&s_sum[cb + j], lsum[j]);
        atomicAdd(&s_ssq[cb + j], lssq[j]);
    }
    __syncthreads();
    if (tid < DD) {
        atomicAdd(&g_stats[tid], s_sum[tid]);
        atomicAdd(&g_stats[DD + tid], s_ssq[tid]);
    }
}

// ---------------- node BN stats over x = Hu + agg ----------------------------
__global__ void k_node_stats(int N) {
    const int tid = threadIdx.x;
    const int c = tid & 127, half = tid >> 7;
    const int rbase = blockIdx.x * DD + half * 64;
    float s = 0.f, q = 0.f;
    for (int i = 0; i < 64; ++i) {
        int r = rbase + i;
        if (r < N) {
            float x = g_Hu[(size_t)r * DD + c] + g_agg[(size_t)r * DD + c];
            s += x;
            q += x * x;
        }
    }
    atomicAdd(&g_stats[2 * DD + c], s);
    atomicAdd(&g_stats[3 * DD + c], q);
}

__global__ void k_bn_final(const float* __restrict__ ge, const float* __restrict__ be,
                           const float* __restrict__ gn, const float* __restrict__ bnb,
                           int E, int N) {
    const int tid = threadIdx.x;
    if (tid < DD) {
        float inv = 1.0f / (float)E;
        float mean = g_stats[tid] * inv;
        float var  = g_stats[DD + tid] * inv - mean * mean;
        float sc   = ge[tid] * rsqrtf(var + 1e-5f);
        g_bnp[tid]      = sc;
        g_bnp[DD + tid] = be[tid] - mean * sc;
    } else if (tid < 2 * DD) {
        int c = tid - DD;
        float inv = 1.0f / (float)N;
        float mean = g_stats[2 * DD + c] * inv;
        float var  = g_stats[3 * DD + c] * inv - mean * mean;
        float sc   = gn[c] * rsqrtf(var + 1e-5f);
        g_bnp[2 * DD + c] = sc;
        g_bnp[3 * DD + c] = bnb[c] - mean * sc;
    }
}

// ---- fused edge MLP: e_new = e + relu(BN(ehat)@W1+b1)@W2 + b2 ---------------
// Single 128KB smem buffer: holds BN(ehat) tile for GEMM1, then is overwritten
// with the XOR-swizzled transposed relu-hidden tile for GEMM2.
__global__ void __launch_bounds__(512, 1)
k_edge_mlp(const float* __restrict__ e, const float* __restrict__ W1,
           const float* __restrict__ b1, const float* __restrict__ W2,
           const float* __restrict__ b2, float* __restrict__ out_e, int E) {
    extern __shared__ float sm[];
    float* Buf = sm;  // RT*DD floats = 128KB
    const int tid = threadIdx.x;
    const long long e0 = (long long)blockIdx.x * RT;

    {   // transpose-load ehat tile with BN applied on the fly
        int r = tid & 255, kh = tid >> 8;
        long long row = e0 + r;
        const float4* ep  = (const float4*)(g_ehat + row * DD) + kh * 16;
        const float4* sc4 = ((const float4*)(g_bnp)) + kh * 16;
        const float4* sh4 = ((const float4*)(g_bnp + DD)) + kh * 16;
        if (row < E) {
#pragma unroll
            for (int m = 0; m < 16; ++m) {
                float4 v = ep[m];
                float4 s = sc4[m];
                float4 t = sh4[m];
                int k = kh * 64 + m * 4;
                Buf[(k) * RT + r]     = fmaf(v.x, s.x, t.x);
                Buf[(k + 1) * RT + r] = fmaf(v.y, s.y, t.y);
                Buf[(k + 2) * RT + r] = fmaf(v.z, s.z, t.z);
                Buf[(k + 3) * RT + r] = fmaf(v.w, s.w, t.w);
            }
        } else {
#pragma unroll
            for (int m = 0; m < 16; ++m) {
                int k = kh * 64 + m * 4;
                Buf[(k) * RT + r] = 0.f; Buf[(k + 1) * RT + r] = 0.f;
                Buf[(k + 2) * RT + r] = 0.f; Buf[(k + 3) * RT + r] = 0.f;
            }
        }
    }
    __syncthreads();

    const int tx = tid & 15, ty = tid >> 4;
    const int cb = tx * 8;
    u64 acc[8][4];
    zero_acc(acc);
    gemm_g<false>(Buf, W1, tx, ty, acc);
    __syncthreads();  // everyone done reading Buf before overwrite

    {   // bias + relu, store hidden transposed with XOR chunk swizzle
        float4 b1a = *(const float4*)(b1 + cb);
        float4 b1b = *(const float4*)(b1 + cb + 4);
        float tb[8] = {b1a.x, b1a.y, b1a.z, b1a.w, b1b.x, b1b.y, b1b.z, b1b.w};
        int key = tx & 7;
#pragma unroll
        for (int j = 0; j < 8; ++j) {
            int c = cb + j;
            int jj = j >> 1;
            float f0, f1, f2, f3, f4, f5, f6, f7;
            if (j & 1) {
                f0 = up2(acc[0][jj]).y; f1 = up2(acc[1][jj]).y;
                f2 = up2(acc[2][jj]).y; f3 = up2(acc[3][jj]).y;
                f4 = up2(acc[4][jj]).y; f5 = up2(acc[5][jj]).y;
                f6 = up2(acc[6][jj]).y; f7 = up2(acc[7][jj]).y;
            } else {
                f0 = up2(acc[0][jj]).x; f1 = up2(acc[1][jj]).x;
                f2 = up2(acc[2][jj]).x; f3 = up2(acc[3][jj]).x;
                f4 = up2(acc[4][jj]).x; f5 = up2(acc[5][jj]).x;
                f6 = up2(acc[6][jj]).x; f7 = up2(acc[7][jj]).x;
            }
            float4 t0 = make_float4(fmaxf(f0 + tb[j], 0.f), fmaxf(f1 + tb[j], 0.f),
                                    fmaxf(f2 + tb[j], 0.f), fmaxf(f3 + tb[j], 0.f));
            float4 t1 = make_float4(fmaxf(f4 + tb[j], 0.f), fmaxf(f5 + tb[j], 0.f),
                                    fmaxf(f6 + tb[j], 0.f), fmaxf(f7 + tb[j], 0.f));
            *(float4*)(Buf + c * RT + (((ty * 2) ^ key) << 2))     = t0;
            *(float4*)(Buf + c * RT + (((ty * 2 + 1) ^ key) << 2)) = t1;
        }
    }
    __syncthreads();

    zero_acc(acc);
    gemm_g<true>(Buf, W2, tx, ty, acc);

    float4 b2a = *(const float4*)(b2 + cb);
    float4 b2b = *(const float4*)(b2 + cb + 4);
#pragma unroll
    for (int i = 0; i < 8; ++i) {
        long long row = e0 + ty * 8 + i;
        if (row < E) {
            float2 p0 = up2(acc[i][0]), p1 = up2(acc[i][1]);
            float2 p2 = up2(acc[i][2]), p3 = up2(acc[i][3]);
            const float* ein = e + (size_t)row * DD + cb;
            float4 e0v = *(const float4*)ein, e1v = *(const float4*)(ein + 4);
            float* op = out_e + (size_t)row * DD + cb;
            *(float4*)op = make_float4(p0.x + b2a.x + e0v.x, p0.y + b2a.y + e0v.y,
                                       p1.x + b2a.z + e0v.z, p1.y + b2a.w + e0v.w);
            *(float4*)(op + 4) = make_float4(p2.x + b2b.x + e1v.x, p2.y + b2b.y + e1v.y,
                                             p3.x + b2b.z + e1v.z, p3.y + b2b.w + e1v.w);
        }
    }
}

// ---- node finalize: h_new = h + alpha * (scale_n*(Hu+agg) + shift_n) --------
__global__ void k_node_final(const float* __restrict__ h, const float* __restrict__ alpha,
                             float* __restrict__ out, int N) {
    size_t i = (size_t)blockIdx.x * blockDim.x + threadIdx.x;  // float4 index
    size_t total = (size_t)N * (DD / 4);
    if (i >= total) return;
    int c4 = (int)(i & 31);
    float4 xu = ((const float4*)g_Hu)[i];
    float4 ag = ((const float4*)g_agg)[i];
    float4 sc = ((const float4*)(g_bnp + 2 * DD))[c4];
    float4 sh = ((const float4*)(g_bnp + 3 * DD))[c4];
    float4 hv = ((const float4*)h)[i];
    float a = *alpha;
    float4 o;
    o.x = hv.x + a * fmaf(xu.x + ag.x, sc.x, sh.x);
    o.y = hv.y + a * fmaf(xu.y + ag.y, sc.y, sh.y);
    o.z = hv.z + a * fmaf(xu.z + ag.z, sc.z, sh.z);
    o.w = hv.w + a * fmaf(xu.w + ag.w, sc.w, sh.w);
    ((float4*)out)[i] = o;
}

extern "C" void kernel_launch(void* const* d_in, const int* in_sizes, int n_in,
                              void* d_out, int out_size) {
    const float* h   = (const float*)d_in[0];
    const float* e   = (const float*)d_in[1];
    const int*   ei  = (const int*)d_in[2];
    const float* Pw  = (const float*)d_in[3];
    const float* Qw  = (const float*)d_in[4];
    const float* Rw  = (const float*)d_in[5];
    const float* Uw  = (const float*)d_in[6];
    const float* Vw  = (const float*)d_in[7];
    const float* W1  = (const float*)d_in[8];
    const float* b1  = (const float*)d_in[9];
    const float* W2  = (const float*)d_in[10];
    const float* b2  = (const float*)d_in[11];
    const float* ge  = (const float*)d_in[12];
    const float* be  = (const float*)d_in[13];
    const float* gn  = (const float*)d_in[14];
    const float* bnb = (const float*)d_in[15];
    const float* alpha = (const float*)d_in[16];

    const int N = in_sizes[0] / DD;
    const int E = in_sizes[1] / DD;
    const int* src = ei;
    const int* dst = ei + E;

    float* out_h = (float*)d_out;
    float* out_e = out_h + (size_t)N * DD;

    const int ASZ = RT * DD * sizeof(float);  // 131072
    cudaFuncSetAttribute(k_node_gemm, cudaFuncAttributeMaxDynamicSharedMemorySize, ASZ);
    cudaFuncSetAttribute(k_edge_ehat, cudaFuncAttributeMaxDynamicSharedMemorySize, ASZ);
    cudaFuncSetAttribute(k_edge_mlp,  cudaFuncAttributeMaxDynamicSharedMemorySize, ASZ);

    void* agg_ptr;
    cudaGetSymbolAddress(&agg_ptr, g_agg);
    cudaMemsetAsync(agg_ptr, 0, (size_t)N * DD * sizeof(float), 0);

    const int nb  = (N + RT - 1) / RT;
    const int ebt = (E + RT - 1) / RT;
    const int nb128 = (N + DD - 1) / DD;

    // Launch order chosen so ncu (-s 5 -c 1, memsets counted) captures k_edge_mlp.
    k_node_gemm<<<nb, 512, ASZ>>>(h, Qw, Rw, Vw, Uw, N);          // idx 1 (also zeroes g_stats)
    k_edge_ehat<<<ebt, 512, ASZ>>>(e, src, dst, Pw, E);           // idx 2
    k_node_stats<<<nb128, 256>>>(N);                              // idx 3
    k_bn_final<<<1, 256>>>(ge, be, gn, bnb, E, N);                // idx 4
    k_edge_mlp<<<ebt, 512, ASZ>>>(e, W1, b1, W2, b2, out_e, E);   // idx 5 <- profiled
    const size_t tot4 = (size_t)N * (DD / 4);
    k_node_final<<<(int)((tot4 + 255) / 256), 256>>>(h, alpha, out_h, N);
}